// round 15
// baseline (speedup 1.0000x reference)
#include <cuda_runtime.h>
#include <cuda_fp16.h>
#include <stdint.h>
#include <math.h>

// ---------------------------------------------------------------- constants
#define M_BATCH   8192
#define N_NODES   1023
#define N_PAD     1024
#define K_DIM     1024
#define N_CLASSES 10
#define N_LEAVES  1024

// GEMM tiling: CTA 128x256, 8 warps of 64x64 (2M x 4N), 2-stage cp.async,
// fp16 accumulators (~105 regs) -> 2 CTAs/SM = 16 warps/SM.
#define GBM 128
#define GBN 256
#define GBK 64                        // fp16 per K-chunk = 128B row
#define NCHUNK (K_DIM / GBK)          // 16
#define A_BYTES (GBM * 128)           // 16384 (128 rows x 128B)
#define B_BYTES (GBN * 128)           // 32768 (256 rows x 128B)
#define STAGE_B (A_BYTES + B_BYTES)   // 49152
#define GEMM_SMEM (2 * STAGE_B)       // 98304

// prep kernel block ranges (each thread: 16 floats = 4 float4 -> 2 uint4)
#define PREP_X_BLOCKS 2048            // 8M floats / (256*16)
#define PREP_W_BLOCKS 256             // 1M floats / (256*16)
#define PREP_L_BLOCKS 4
#define PREP_BLOCKS (PREP_X_BLOCKS + PREP_W_BLOCKS + PREP_L_BLOCKS)

// ---------------------------------------------------------------- scratch
__device__ __half g_xh[(size_t)M_BATCH * K_DIM];   // 16 MB (fp16 inputs)
__device__ __half g_wh[(size_t)N_PAD * K_DIM];     // 2 MB (row 1023 zero)
__device__ __half g_probs[(size_t)M_BATCH * N_PAD];// 16 MB
__device__ float g_leaf_reward[N_LEAVES];

// ---------------------------------------------------------------- helpers
__device__ __forceinline__ uint32_t s2u(const void* p) {
    uint32_t a;
    asm("{ .reg .u64 t; cvta.to.shared.u64 t, %1; cvt.u32.u64 %0, t; }"
        : "=r"(a) : "l"(p));
    return a;
}
__device__ __forceinline__ uint32_t swz(uint32_t o) { return o ^ ((o >> 3) & 0x70); }

__device__ __forceinline__ uint32_t h2x(float a, float b) {
    __half2 h = __floats2half2_rn(a, b);
    return *reinterpret_cast<uint32_t*>(&h);
}

#define LDSM_X4(r0, r1, r2, r3, a)                                             \
    asm volatile("ldmatrix.sync.aligned.m8n8.x4.shared.b16 {%0,%1,%2,%3}, [%4];" \
        : "=r"(r0), "=r"(r1), "=r"(r2), "=r"(r3) : "r"(a))

// fp16-accumulator MMA: D(half2 x2) = A x B + D.
#define MMA16816_H(c, a, b0, b1)                                               \
    asm("mma.sync.aligned.m16n8k16.row.col.f16.f16.f16.f16 "                   \
        "{%0,%1}, {%2,%3,%4,%5}, {%6,%7}, {%0,%1};"                            \
        : "+r"((c)[0]), "+r"((c)[1])                                           \
        : "r"((a)[0]), "r"((a)[1]), "r"((a)[2]), "r"((a)[3]),                  \
          "r"(b0), "r"(b1))

// ---------------------------------------------------------------------------
// Kernel 1: fused prep — convert x, convert+pad W (fp32->fp16), leaf_reward.
//   16 floats/thread: 4 independent float4 loads -> 2 uint4 stores (MLP=4).
// ---------------------------------------------------------------------------
__global__ __launch_bounds__(256)
void prep_kernel(const float* __restrict__ x,
                 const float* __restrict__ W,
                 const float* __restrict__ leaf_dist,
                 const float* __restrict__ class_reward) {
    int blk = blockIdx.x;
    if (blk < PREP_X_BLOCKS) {
        size_t base = ((size_t)blk * 256 + threadIdx.x) * 16;
        float4 v0 = *reinterpret_cast<const float4*>(x + base);
        float4 v1 = *reinterpret_cast<const float4*>(x + base + 4);
        float4 v2 = *reinterpret_cast<const float4*>(x + base + 8);
        float4 v3 = *reinterpret_cast<const float4*>(x + base + 12);
        *reinterpret_cast<uint4*>(g_xh + base) =
            make_uint4(h2x(v0.x, v0.y), h2x(v0.z, v0.w),
                       h2x(v1.x, v1.y), h2x(v1.z, v1.w));
        *reinterpret_cast<uint4*>(g_xh + base + 8) =
            make_uint4(h2x(v2.x, v2.y), h2x(v2.z, v2.w),
                       h2x(v3.x, v3.y), h2x(v3.z, v3.w));
    } else if (blk < PREP_X_BLOCKS + PREP_W_BLOCKS) {
        size_t base = ((size_t)(blk - PREP_X_BLOCKS) * 256 + threadIdx.x) * 16;
        int row = (int)(base >> 10);     // 16 floats never straddle a row
        if (row < N_NODES) {
            float4 v0 = *reinterpret_cast<const float4*>(W + base);
            float4 v1 = *reinterpret_cast<const float4*>(W + base + 4);
            float4 v2 = *reinterpret_cast<const float4*>(W + base + 8);
            float4 v3 = *reinterpret_cast<const float4*>(W + base + 12);
            *reinterpret_cast<uint4*>(g_wh + base) =
                make_uint4(h2x(v0.x, v0.y), h2x(v0.z, v0.w),
                           h2x(v1.x, v1.y), h2x(v1.z, v1.w));
            *reinterpret_cast<uint4*>(g_wh + base + 8) =
                make_uint4(h2x(v2.x, v2.y), h2x(v2.z, v2.w),
                           h2x(v3.x, v3.y), h2x(v3.z, v3.w));
        } else {
            *reinterpret_cast<uint4*>(g_wh + base)     = make_uint4(0u, 0u, 0u, 0u);
            *reinterpret_cast<uint4*>(g_wh + base + 8) = make_uint4(0u, 0u, 0u, 0u);
        }
    } else {
        int l = (blk - PREP_X_BLOCKS - PREP_W_BLOCKS) * 256 + threadIdx.x;
        if (l >= N_LEAVES) return;
        float v[N_CLASSES];
        float mx = -1e30f;
#pragma unroll
        for (int c = 0; c < N_CLASSES; c++) {
            v[c] = leaf_dist[l * N_CLASSES + c];
            mx = fmaxf(mx, v[c]);
        }
        float s = 0.f;
#pragma unroll
        for (int c = 0; c < N_CLASSES; c++) { v[c] = expf(v[c] - mx); s += v[c]; }
        float inv = 1.f / s, r = 0.f;
#pragma unroll
        for (int c = 0; c < N_CLASSES; c++) r += v[c] * inv * class_reward[c];
        g_leaf_reward[l] = r;
    }
}

// ---------------------------------------------------------------------------
// Kernel 2: fp16 warp-MMA GEMM, CTA 128x256, 8 warps 2(M)x4(N) of 64x64,
//   2-stage pipeline, 2 CTAs/SM = 16 warps/SM, MMA:LDSM ratio 4.0,
//   per-warp k-step phase rotation. fp16 accumulate (~105 regs, no spill).
// ---------------------------------------------------------------------------
__global__ __launch_bounds__(256, 2)
void gemm_f16_kernel(const float* __restrict__ bvec,
                     const float* __restrict__ beta) {
    extern __shared__ char smem[];
    const uint32_t sb = s2u(smem);
    const int tid  = threadIdx.x;
    const int wid  = tid >> 5, lane = tid & 31;
    const int wm   = wid & 1;            // 0..1 -> 64 M-rows
    const int wn   = wid >> 1;           // 0..3 -> 64 N-cols
    const int m0   = blockIdx.y * GBM;
    const int n0   = blockIdx.x * GBN;

    const int g = lane >> 3;             // ldmatrix 8-thread group
    const int r = lane & 7;

    const __half* ag = g_xh + (size_t)m0 * K_DIM;
    const __half* bg = g_wh + (size_t)n0 * K_DIM;

    // stage loader: A 128x64 (4 lines/thread) + B 256x64 (8 lines/thread)
#define LOAD_STAGE(ck) do {                                                    \
    uint32_t _st = sb + ((ck) & 1) * STAGE_B;                                  \
    _Pragma("unroll")                                                          \
    for (int _u = 0; _u < 4; _u++) {                                           \
        int _c = tid + 256 * _u;                                               \
        int _row = _c >> 3, _seg = _c & 7;                                     \
        uint32_t _off = swz((uint32_t)(_row * 128 + _seg * 16));               \
        const void* _as = ag + (size_t)_row * K_DIM + (ck) * GBK + _seg * 8;   \
        asm volatile("cp.async.cg.shared.global [%0], [%1], 16;"               \
                     :: "r"(_st + _off), "l"(_as));                            \
    }                                                                          \
    _Pragma("unroll")                                                          \
    for (int _u = 0; _u < 8; _u++) {                                           \
        int _c = tid + 256 * _u;                                               \
        int _row = _c >> 3, _seg = _c & 7;                                     \
        uint32_t _off = swz((uint32_t)(_row * 128 + _seg * 16));               \
        const void* _bs = bg + (size_t)_row * K_DIM + (ck) * GBK + _seg * 8;   \
        asm volatile("cp.async.cg.shared.global [%0], [%1], 16;"               \
                     :: "r"(_st + A_BYTES + _off), "l"(_bs));                  \
    }                                                                          \
    asm volatile("cp.async.commit_group;" ::: "memory");                       \
} while (0)

    uint32_t acc[4][8][2];               // fp16 acc: 4 m16 x 8 n8 x half2-pair
#pragma unroll
    for (int i = 0; i < 4; i++)
#pragma unroll
        for (int j = 0; j < 8; j++) { acc[i][j][0] = 0u; acc[i][j][1] = 0u; }

    const int a_kadd = (g >> 1) * 16;
    const int b_kadd = (g & 1) * 16;
    const int srot   = wid & 3;          // per-warp k-step phase offset

    LOAD_STAGE(0);

    for (int it = 0; it < NCHUNK; it++) {
        if (it + 1 < NCHUNK) {
            LOAD_STAGE(it + 1);
            asm volatile("cp.async.wait_group 1;" ::: "memory");
        } else {
            asm volatile("cp.async.wait_group 0;" ::: "memory");
        }
        __syncthreads();

        const uint32_t stA = sb + (it & 1) * STAGE_B;
        const uint32_t stB = stA + A_BYTES;

#pragma unroll
        for (int s0 = 0; s0 < 4; s0++) {         // rotated k16 step order
            const int s = (s0 + srot) & 3;
            uint32_t a[4][4];
#pragma unroll
            for (int i = 0; i < 4; i++) {
                int row = wm * 64 + i * 16 + r + (g & 1) * 8;
                uint32_t addr = stA + (uint32_t)(row * 128)
                              + (uint32_t)((s * 32 + a_kadd) ^ ((row & 7) * 16));
                LDSM_X4(a[i][0], a[i][1], a[i][2], a[i][3], addr);
            }
#pragma unroll
            for (int j = 0; j < 4; j++) {        // n16 group: load then consume
                int row = wn * 64 + j * 16 + r + (g >> 1) * 8;
                uint32_t addr = stB + (uint32_t)(row * 128)
                              + (uint32_t)((s * 32 + b_kadd) ^ ((row & 7) * 16));
                uint32_t b0, b1, b2, b3;
                LDSM_X4(b0, b1, b2, b3, addr);
#pragma unroll
                for (int i = 0; i < 4; i++) {
                    MMA16816_H(acc[i][2 * j],     a[i], b0, b1);
                    MMA16816_H(acc[i][2 * j + 1], a[i], b2, b3);
                }
            }
        }
        __syncthreads();   // protect this stage's buffer before next LOAD
    }

    // ---- stage bias/beta (reuse stage smem), then fused sigmoid + fp16 store
    float* bs = reinterpret_cast<float*>(smem);
    float* es = bs + GBN;
    {
        int n = n0 + tid;
        bs[tid] = (n < N_NODES) ? bvec[n] : 0.f;
        es[tid] = (n < N_NODES) ? beta[n] : 0.f;
    }
    __syncthreads();

    const int qr = lane >> 2;          // 0..7
    const int qc = lane & 3;           // 0..3
#pragma unroll
    for (int i = 0; i < 4; i++) {
        int mA = m0 + wm * 64 + i * 16 + qr;
#pragma unroll
        for (int j = 0; j < 8; j++) {
            int nl = wn * 64 + j * 8 + 2 * qc;
            float b0 = bs[nl],     e0 = es[nl];
            float b1 = bs[nl + 1], e1 = es[nl + 1];
            __half2 d0 = *reinterpret_cast<__half2*>(&acc[i][j][0]);
            __half2 d1 = *reinterpret_cast<__half2*>(&acc[i][j][1]);
            float z0 = e0 * (__low2float(d0)  + b0);
            float z1 = e1 * (__high2float(d0) + b1);
            float z2 = e0 * (__low2float(d1)  + b0);
            float z3 = e1 * (__high2float(d1) + b1);
            __half2 v0 = __floats2half2_rn(1.f / (1.f + __expf(-z0)),
                                           1.f / (1.f + __expf(-z1)));
            __half2 v1 = __floats2half2_rn(1.f / (1.f + __expf(-z2)),
                                           1.f / (1.f + __expf(-z3)));
            *reinterpret_cast<__half2*>(&g_probs[(size_t)mA * N_PAD + n0 + nl]) = v0;
            *reinterpret_cast<__half2*>(&g_probs[(size_t)(mA + 8) * N_PAD + n0 + nl]) = v1;
        }
    }
}

// ---------------------------------------------------------------------------
// Kernel 3: warp-per-row tree fold (unchanged — measured fast)
// ---------------------------------------------------------------------------
#define FOLD_ROWS 8
__device__ __forceinline__ int lpad(int i) { return i + (i >> 5); }

__global__ __launch_bounds__(256)
void fold_kernel(float* __restrict__ out) {
    __shared__ float Lr[N_LEAVES + N_LEAVES / 32];

    const int tid  = threadIdx.x;
    const int wrp  = tid >> 5;
    const int lane = tid & 31;
    const int row  = blockIdx.x * FOLD_ROWS + wrp;

    for (int i = tid; i < N_LEAVES; i += 256) Lr[lpad(i)] = g_leaf_reward[i];
    __syncthreads();

    const __half* p = g_probs + (size_t)row * N_PAD;

    float v[16];
    {
        const int base9 = 511 + 16 * lane;
#pragma unroll
        for (int i = 0; i < 16; i++) {
            float pp = __half2float(__ldg(p + base9 + i));
            float l0 = Lr[lpad(32 * lane + 2 * i)];
            float l1 = Lr[lpad(32 * lane + 2 * i + 1)];
            v[i] = pp * l0 + (1.f - pp) * l1;
        }
        const int base8 = 255 + 8 * lane;
#pragma unroll
        for (int i = 0; i < 8; i++) {
            float pp = __half2float(__ldg(p + base8 + i));
            v[i] = pp * v[2 * i] + (1.f - pp) * v[2 * i + 1];
        }
        const int base7 = 127 + 4 * lane;
#pragma unroll
        for (int i = 0; i < 4; i++) {
            float pp = __half2float(__ldg(p + base7 + i));
            v[i] = pp * v[2 * i] + (1.f - pp) * v[2 * i + 1];
        }
        const int base6 = 63 + 2 * lane;
#pragma unroll
        for (int i = 0; i < 2; i++) {
            float pp = __half2float(__ldg(p + base6 + i));
            v[i] = pp * v[2 * i] + (1.f - pp) * v[2 * i + 1];
        }
        float pp = __half2float(__ldg(p + 31 + lane));
        v[0] = pp * v[0] + (1.f - pp) * v[1];
    }

    float vv = v[0];
#pragma unroll
    for (int lvl = 4; lvl >= 0; lvl--) {
        int cnt = 1 << lvl;
        float vl = __shfl_sync(0xFFFFFFFFu, vv, 2 * lane);
        float vr = __shfl_sync(0xFFFFFFFFu, vv, 2 * lane + 1);
        float pp = (lane < cnt) ? __half2float(__ldg(p + cnt - 1 + lane)) : 0.f;
        vv = pp * vl + (1.f - pp) * vr;
    }
    if (lane == 0) out[row] = vv;
}

// ---------------------------------------------------------------------------
// kernel_launch: x, W, b, beta, leaf_dist, class_reward -> loss[8192]
// ---------------------------------------------------------------------------
extern "C" void kernel_launch(void* const* d_in, const int* in_sizes, int n_in,
                              void* d_out, int out_size) {
    const float* x            = (const float*)d_in[0];
    const float* W            = (const float*)d_in[1];
    const float* b            = (const float*)d_in[2];
    const float* beta         = (const float*)d_in[3];
    const float* leaf_dist    = (const float*)d_in[4];
    const float* class_reward = (const float*)d_in[5];
    float* out = (float*)d_out;

    cudaFuncSetAttribute(gemm_f16_kernel,
                         cudaFuncAttributeMaxDynamicSharedMemorySize, GEMM_SMEM);

    prep_kernel<<<PREP_BLOCKS, 256>>>(x, W, leaf_dist, class_reward);

    dim3 grid(N_PAD / GBN, M_BATCH / GBM);   // 4 x 64 = 256 CTAs
    gemm_f16_kernel<<<grid, 256, GEMM_SMEM>>>(b, beta);

    fold_kernel<<<M_BATCH / FOLD_ROWS, 256>>>(out);
}

// round 17
// speedup vs baseline: 1.0526x; 1.0526x over previous
#include <cuda_runtime.h>
#include <cuda_fp16.h>
#include <stdint.h>
#include <math.h>

// ---------------------------------------------------------------- constants
#define M_BATCH   8192
#define N_NODES   1023
#define N_PAD     1024
#define K_DIM     1024
#define N_CLASSES 10
#define N_LEAVES  1024

// GEMM tiling (R13, proven best): CTA 128x128, 4 warps of 64x64 (2M x 2N),
// 2-stage cp.async, fp16 accumulators -> 3 CTAs/SM.
#define GBM 128
#define GBN 128
#define GBK 64                        // fp16 per K-chunk = 128B row
#define NCHUNK (K_DIM / GBK)          // 16
#define TILE_B 16384                  // one 128x64 fp16 tile, bytes
#define STAGE_B (2 * TILE_B)          // A+B per stage
#define GEMM_SMEM (2 * STAGE_B)       // 65536

// prep split: x half0 (rows 0..4095) + W + leaf in prep_main; x half1 in prep_x2
#define PREP_X0_BLOCKS 2048           // 4M floats / (256*8)
#define PREP_W_BLOCKS  512
#define PREP_L_BLOCKS  4
#define PREP_MAIN_BLOCKS (PREP_X0_BLOCKS + PREP_W_BLOCKS + PREP_L_BLOCKS)
#define PREP_X1_BLOCKS 2048

// ---------------------------------------------------------------- scratch
__device__ __half g_xh[(size_t)M_BATCH * K_DIM];   // 16 MB (fp16 inputs)
__device__ __half g_wh[(size_t)N_PAD * K_DIM];     // 2 MB (row 1023 zero)
__device__ __half g_probs[(size_t)M_BATCH * N_PAD];// 16 MB
__device__ float g_leaf_reward[N_LEAVES];

// ---------------------------------------------------------------- helpers
__device__ __forceinline__ uint32_t s2u(const void* p) {
    uint32_t a;
    asm("{ .reg .u64 t; cvta.to.shared.u64 t, %1; cvt.u32.u64 %0, t; }"
        : "=r"(a) : "l"(p));
    return a;
}
__device__ __forceinline__ uint32_t swz(uint32_t o) { return o ^ ((o >> 3) & 0x70); }

__device__ __forceinline__ uint32_t h2x(float a, float b) {
    __half2 h = __floats2half2_rn(a, b);
    return *reinterpret_cast<uint32_t*>(&h);
}

#define LDSM_X4(r0, r1, r2, r3, a)                                             \
    asm volatile("ldmatrix.sync.aligned.m8n8.x4.shared.b16 {%0,%1,%2,%3}, [%4];" \
        : "=r"(r0), "=r"(r1), "=r"(r2), "=r"(r3) : "r"(a))

#define MMA16816_H(c, a, b0, b1)                                               \
    asm("mma.sync.aligned.m16n8k16.row.col.f16.f16.f16.f16 "                   \
        "{%0,%1}, {%2,%3,%4,%5}, {%6,%7}, {%0,%1};"                            \
        : "+r"((c)[0]), "+r"((c)[1])                                           \
        : "r"((a)[0]), "r"((a)[1]), "r"((a)[2]), "r"((a)[3]),                  \
          "r"(b0), "r"(b1))

// ---------------------------------------------------------------------------
// Kernel 1a: prep_main — x rows [0,4096) + W (padded) + leaf_reward.
// ---------------------------------------------------------------------------
__global__ __launch_bounds__(256)
void prep_main(const float* __restrict__ x,
               const float* __restrict__ W,
               const float* __restrict__ leaf_dist,
               const float* __restrict__ class_reward) {
    int blk = blockIdx.x;
    if (blk < PREP_X0_BLOCKS) {
        size_t base = ((size_t)blk * 256 + threadIdx.x) * 8;
        float4 v0 = *reinterpret_cast<const float4*>(x + base);
        float4 v1 = *reinterpret_cast<const float4*>(x + base + 4);
        *reinterpret_cast<uint4*>(g_xh + base) =
            make_uint4(h2x(v0.x, v0.y), h2x(v0.z, v0.w),
                       h2x(v1.x, v1.y), h2x(v1.z, v1.w));
    } else if (blk < PREP_X0_BLOCKS + PREP_W_BLOCKS) {
        size_t base = ((size_t)(blk - PREP_X0_BLOCKS) * 256 + threadIdx.x) * 8;
        int row = (int)(base >> 10);
        uint4 o;
        if (row < N_NODES) {
            float4 v0 = *reinterpret_cast<const float4*>(W + base);
            float4 v1 = *reinterpret_cast<const float4*>(W + base + 4);
            o = make_uint4(h2x(v0.x, v0.y), h2x(v0.z, v0.w),
                           h2x(v1.x, v1.y), h2x(v1.z, v1.w));
        } else {
            o = make_uint4(0u, 0u, 0u, 0u);
        }
        *reinterpret_cast<uint4*>(g_wh + base) = o;
    } else {
        int l = (blk - PREP_X0_BLOCKS - PREP_W_BLOCKS) * 256 + threadIdx.x;
        if (l >= N_LEAVES) return;
        float v[N_CLASSES];
        float mx = -1e30f;
#pragma unroll
        for (int c = 0; c < N_CLASSES; c++) {
            v[c] = leaf_dist[l * N_CLASSES + c];
            mx = fmaxf(mx, v[c]);
        }
        float s = 0.f;
#pragma unroll
        for (int c = 0; c < N_CLASSES; c++) { v[c] = expf(v[c] - mx); s += v[c]; }
        float inv = 1.f / s, r = 0.f;
#pragma unroll
        for (int c = 0; c < N_CLASSES; c++) r += v[c] * inv * class_reward[c];
        g_leaf_reward[l] = r;
    }
}

// ---------------------------------------------------------------------------
// Kernel 1b: prep_x2 — x rows [4096, 8192). Runs concurrent with gemm half0.
// ---------------------------------------------------------------------------
__global__ __launch_bounds__(256)
void prep_x2(const float* __restrict__ x) {
    size_t base = (((size_t)blockIdx.x + PREP_X0_BLOCKS) * 256 + threadIdx.x) * 8;
    float4 v0 = *reinterpret_cast<const float4*>(x + base);
    float4 v1 = *reinterpret_cast<const float4*>(x + base + 4);
    *reinterpret_cast<uint4*>(g_xh + base) =
        make_uint4(h2x(v0.x, v0.y), h2x(v0.z, v0.w),
                   h2x(v1.x, v1.y), h2x(v1.z, v1.w));
}

// ---------------------------------------------------------------------------
// Kernel 2: fp16 warp-MMA GEMM (R13 body verbatim + m_base param).
// ---------------------------------------------------------------------------
__global__ __launch_bounds__(128, 3)
void gemm_f16_kernel(const float* __restrict__ bvec,
                     const float* __restrict__ beta,
                     int m_base) {
    extern __shared__ char smem[];
    const uint32_t sb = s2u(smem);
    const int tid  = threadIdx.x;
    const int wid  = tid >> 5, lane = tid & 31;
    const int wm   = wid & 1;            // 0..1 -> 64 M-rows
    const int wn   = wid >> 1;           // 0..1 -> 64 N-cols
    const int m0   = m_base + blockIdx.y * GBM;
    const int n0   = blockIdx.x * GBN;

    const int g = lane >> 3;             // ldmatrix 8-thread group
    const int r = lane & 7;

    const __half* ag = g_xh + (size_t)m0 * K_DIM;
    const __half* bg = g_wh + (size_t)n0 * K_DIM;

#define LOAD_STAGE(ck) do {                                                    \
    uint32_t _st = sb + ((ck) & 1) * STAGE_B;                                  \
    _Pragma("unroll")                                                          \
    for (int _u = 0; _u < 8; _u++) {                                           \
        int _c = tid + 128 * _u;                                               \
        int _row = _c >> 3, _seg = _c & 7;                                     \
        uint32_t _off = swz((uint32_t)(_row * 128 + _seg * 16));               \
        const void* _as = ag + (size_t)_row * K_DIM + (ck) * GBK + _seg * 8;   \
        const void* _bs = bg + (size_t)_row * K_DIM + (ck) * GBK + _seg * 8;   \
        asm volatile("cp.async.cg.shared.global [%0], [%1], 16;"               \
                     :: "r"(_st + _off), "l"(_as));                            \
        asm volatile("cp.async.cg.shared.global [%0], [%1], 16;"               \
                     :: "r"(_st + TILE_B + _off), "l"(_bs));                   \
    }                                                                          \
    asm volatile("cp.async.commit_group;" ::: "memory");                       \
} while (0)

    uint32_t acc[4][8][2];               // fp16 acc: 4 m16 x 8 n8 x half2-pair
#pragma unroll
    for (int i = 0; i < 4; i++)
#pragma unroll
        for (int j = 0; j < 8; j++) { acc[i][j][0] = 0u; acc[i][j][1] = 0u; }

    const int a_kadd = (g >> 1) * 16;
    const int b_kadd = (g & 1) * 16;
    const int srot   = wid & 3;          // per-warp k-step phase offset

    LOAD_STAGE(0);

    for (int it = 0; it < NCHUNK; it++) {
        if (it + 1 < NCHUNK) {
            LOAD_STAGE(it + 1);
            asm volatile("cp.async.wait_group 1;" ::: "memory");
        } else {
            asm volatile("cp.async.wait_group 0;" ::: "memory");
        }
        __syncthreads();

        const uint32_t stA = sb + (it & 1) * STAGE_B;
        const uint32_t stB = stA + TILE_B;

#pragma unroll
        for (int s0 = 0; s0 < 4; s0++) {         // rotated k16 step order
            const int s = (s0 + srot) & 3;
            uint32_t a[4][4];
#pragma unroll
            for (int i = 0; i < 4; i++) {
                int row = wm * 64 + i * 16 + r + (g & 1) * 8;
                uint32_t addr = stA + (uint32_t)(row * 128)
                              + (uint32_t)((s * 32 + a_kadd) ^ ((row & 7) * 16));
                LDSM_X4(a[i][0], a[i][1], a[i][2], a[i][3], addr);
            }
#pragma unroll
            for (int j = 0; j < 4; j++) {        // n16 group: load then consume
                int row = wn * 64 + j * 16 + r + (g >> 1) * 8;
                uint32_t addr = stB + (uint32_t)(row * 128)
                              + (uint32_t)((s * 32 + b_kadd) ^ ((row & 7) * 16));
                uint32_t b0, b1, b2, b3;
                LDSM_X4(b0, b1, b2, b3, addr);
#pragma unroll
                for (int i = 0; i < 4; i++) {
                    MMA16816_H(acc[i][2 * j],     a[i], b0, b1);
                    MMA16816_H(acc[i][2 * j + 1], a[i], b2, b3);
                }
            }
        }
        __syncthreads();   // protect this stage's buffer before next LOAD
    }

    // ---- stage bias/beta (reuse stage smem), then fused sigmoid + fp16 store
    float* bs = reinterpret_cast<float*>(smem);
    float* es = bs + 128;
    if (tid < 128) {
        int n = n0 + tid;
        bs[tid] = (n < N_NODES) ? bvec[n] : 0.f;
        es[tid] = (n < N_NODES) ? beta[n] : 0.f;
    }
    __syncthreads();

    const int qr = lane >> 2;          // 0..7
    const int qc = lane & 3;           // 0..3
#pragma unroll
    for (int i = 0; i < 4; i++) {
        int mA = m0 + wm * 64 + i * 16 + qr;
#pragma unroll
        for (int j = 0; j < 8; j++) {
            int nl = wn * 64 + j * 8 + 2 * qc;
            float b0 = bs[nl],     e0 = es[nl];
            float b1 = bs[nl + 1], e1 = es[nl + 1];
            __half2 d0 = *reinterpret_cast<__half2*>(&acc[i][j][0]);
            __half2 d1 = *reinterpret_cast<__half2*>(&acc[i][j][1]);
            float z0 = e0 * (__low2float(d0)  + b0);
            float z1 = e1 * (__high2float(d0) + b1);
            float z2 = e0 * (__low2float(d1)  + b0);
            float z3 = e1 * (__high2float(d1) + b1);
            __half2 v0 = __floats2half2_rn(1.f / (1.f + __expf(-z0)),
                                           1.f / (1.f + __expf(-z1)));
            __half2 v1 = __floats2half2_rn(1.f / (1.f + __expf(-z2)),
                                           1.f / (1.f + __expf(-z3)));
            *reinterpret_cast<__half2*>(&g_probs[(size_t)mA * N_PAD + n0 + nl]) = v0;
            *reinterpret_cast<__half2*>(&g_probs[(size_t)(mA + 8) * N_PAD + n0 + nl]) = v1;
        }
    }
}

// ---------------------------------------------------------------------------
// Kernel 3: warp-per-row tree fold (unchanged — measured fast)
// ---------------------------------------------------------------------------
#define FOLD_ROWS 8
__device__ __forceinline__ int lpad(int i) { return i + (i >> 5); }

__global__ __launch_bounds__(256)
void fold_kernel(float* __restrict__ out) {
    __shared__ float Lr[N_LEAVES + N_LEAVES / 32];

    const int tid  = threadIdx.x;
    const int wrp  = tid >> 5;
    const int lane = tid & 31;
    const int row  = blockIdx.x * FOLD_ROWS + wrp;

    for (int i = tid; i < N_LEAVES; i += 256) Lr[lpad(i)] = g_leaf_reward[i];
    __syncthreads();

    const __half* p = g_probs + (size_t)row * N_PAD;

    float v[16];
    {
        const int base9 = 511 + 16 * lane;
#pragma unroll
        for (int i = 0; i < 16; i++) {
            float pp = __half2float(__ldg(p + base9 + i));
            float l0 = Lr[lpad(32 * lane + 2 * i)];
            float l1 = Lr[lpad(32 * lane + 2 * i + 1)];
            v[i] = pp * l0 + (1.f - pp) * l1;
        }
        const int base8 = 255 + 8 * lane;
#pragma unroll
        for (int i = 0; i < 8; i++) {
            float pp = __half2float(__ldg(p + base8 + i));
            v[i] = pp * v[2 * i] + (1.f - pp) * v[2 * i + 1];
        }
        const int base7 = 127 + 4 * lane;
#pragma unroll
        for (int i = 0; i < 4; i++) {
            float pp = __half2float(__ldg(p + base7 + i));
            v[i] = pp * v[2 * i] + (1.f - pp) * v[2 * i + 1];
        }
        const int base6 = 63 + 2 * lane;
#pragma unroll
        for (int i = 0; i < 2; i++) {
            float pp = __half2float(__ldg(p + base6 + i));
            v[i] = pp * v[2 * i] + (1.f - pp) * v[2 * i + 1];
        }
        float pp = __half2float(__ldg(p + 31 + lane));
        v[0] = pp * v[0] + (1.f - pp) * v[1];
    }

    float vv = v[0];
#pragma unroll
    for (int lvl = 4; lvl >= 0; lvl--) {
        int cnt = 1 << lvl;
        float vl = __shfl_sync(0xFFFFFFFFu, vv, 2 * lane);
        float vr = __shfl_sync(0xFFFFFFFFu, vv, 2 * lane + 1);
        float pp = (lane < cnt) ? __half2float(__ldg(p + cnt - 1 + lane)) : 0.f;
        vv = pp * vl + (1.f - pp) * vr;
    }
    if (lane == 0) out[row] = vv;
}

// ---------------------------------------------------------------------------
// kernel_launch: forked-stream pipeline (capture-legal events):
//   s0: prep_main ──► gemm(half0) ───────────────┐
//        └─evA─► s1: prep_x2 ─► gemm(half1) ─evB─┴─► s0: fold
// ---------------------------------------------------------------------------
extern "C" void kernel_launch(void* const* d_in, const int* in_sizes, int n_in,
                              void* d_out, int out_size) {
    const float* x            = (const float*)d_in[0];
    const float* W            = (const float*)d_in[1];
    const float* b            = (const float*)d_in[2];
    const float* beta         = (const float*)d_in[3];
    const float* leaf_dist    = (const float*)d_in[4];
    const float* class_reward = (const float*)d_in[5];
    float* out = (float*)d_out;

    // All host-side setup before any launch. Fresh per call: deterministic,
    // no static guards, no device allocation.
    cudaStream_t s1;
    cudaEvent_t evA, evB;
    cudaStreamCreateWithFlags(&s1, cudaStreamNonBlocking);
    cudaEventCreateWithFlags(&evA, cudaEventDisableTiming);
    cudaEventCreateWithFlags(&evB, cudaEventDisableTiming);
    cudaFuncSetAttribute(gemm_f16_kernel,
                         cudaFuncAttributeMaxDynamicSharedMemorySize, GEMM_SMEM);

    dim3 grid(N_PAD / GBN, (M_BATCH / 2) / GBM);   // 8 x 32 per half

    // s0: prep rows 0..4095 (+W+leaf), then GEMM half0
    prep_main<<<PREP_MAIN_BLOCKS, 256>>>(x, W, leaf_dist, class_reward);
    cudaEventRecord(evA, 0);
    gemm_f16_kernel<<<grid, 128, GEMM_SMEM>>>(b, beta, 0);

    // s1: fork after prep_main; prep rows 4096..8191 overlaps GEMM half0,
    // then GEMM half1 (ordered after prep_x2 within s1).
    cudaStreamWaitEvent(s1, evA, 0);
    prep_x2<<<PREP_X1_BLOCKS, 256, 0, s1>>>(x);
    gemm_f16_kernel<<<grid, 128, GEMM_SMEM, s1>>>(b, beta, M_BATCH / 2);
    cudaEventRecord(evB, s1);

    // join back into s0, then fold
    cudaStreamWaitEvent(0, evB, 0);
    fold_kernel<<<M_BATCH / FOLD_ROWS, 256>>>(out);
}